// round 9
// baseline (speedup 1.0000x reference)
#include <cuda_runtime.h>
#include <cuda_bf16.h>
#include <math.h>
#include <stdint.h>

#define NTOT 1024
#define NI   64
#define NC   960
#define NR   896
#define WARM 25
#define FULL 0xffffffffu

// ---------------- device scratch ----------------
__device__ __align__(16) __nv_bfloat16 g_Bh[NC * 64];
__device__ __align__(16) __nv_bfloat16 g_Bl[NC * 64];
__device__ __align__(16) float g_Ep[NR], g_Em[NR], g_Ip[NR], g_Im[NR];
__device__ __align__(16) int   g_pidx_e[NR], g_pidx_i[NR];
__device__ __align__(16) int   g_pos_e[NC], g_pos_i[NC];
__device__ __align__(16) float g_Tp[NC], g_Tm[NC], g_ctop[NC];
__device__ __align__(16) float g_base[NC];

__device__ __forceinline__ uint32_t smem_u32(const void* p) {
    uint32_t a;
    asm("{ .reg .u64 t; cvta.to.shared.u64 t, %1; cvt.u32.u64 %0, t; }" : "=r"(a) : "l"(p));
    return a;
}
#define SW128(x) ((x) ^ (((x) >> 3) & 0x70))

#define LDSM_X4(r0, r1, r2, r3, a) \
    asm volatile("ldmatrix.sync.aligned.m8n8.x4.shared.b16 {%0,%1,%2,%3}, [%4];" \
        : "=r"(r0), "=r"(r1), "=r"(r2), "=r"(r3) : "r"(a))

#define MMA16816(d, a, b0, b1) \
    asm volatile("mma.sync.aligned.m16n8k16.row.col.f32.bf16.bf16.f32 " \
        "{%0,%1,%2,%3}, {%4,%5,%6,%7}, {%8,%9}, {%0,%1,%2,%3};" \
        : "+f"((d)[0]), "+f"((d)[1]), "+f"((d)[2]), "+f"((d)[3]) \
        : "r"((a)[0]), "r"((a)[1]), "r"((a)[2]), "r"((a)[3]), "r"(b0), "r"(b1))

// =================== k_init: all tables (R7 form, proven 6.4us) =============
__global__ void k_init(const float* __restrict__ ident, const float* __restrict__ enh,
                       const float* __restrict__ inh,  const float* __restrict__ beta) {
    const int b = blockIdx.x, t = threadIdx.x;
    const int wid = t >> 5, lane = t & 31;
    const float bb = beta[0];

    if (b < 240) {                       // bf16-split B matrix [j][k]
        int idx = b * 256 + t;
        int j = idx >> 6, k = idx & 63;
        float id = ident[NI + j];
        float v = expf(-bb * fabsf(enh[k] - id)) - expf(-bb * fabsf(inh[k] - id));
        __nv_bfloat16 h = __float2bfloat16(v);
        __nv_bfloat16 l = __float2bfloat16(v - __bfloat162float(h));
        g_Bh[idx] = h;
        g_Bl[idx] = l;
    } else if (b < 464) {                // ranks + permuted exp tables
        bool is_e = (b < 352);
        const float* arr = is_e ? enh : inh;
        int k = ((b - (is_e ? 240 : 352)) * 8 + wid);
        float x = arr[128 + k];
        int cnt = 0;
        for (int k2 = lane; k2 < NR; k2 += 32) {
            float y = arr[128 + k2];
            cnt += (y < x) || (y == x && k2 < k);
        }
        #pragma unroll
        for (int o = 16; o; o >>= 1) cnt += __shfl_xor_sync(FULL, cnt, o);
        if (lane == 0) {
            if (is_e) { g_pidx_e[cnt] = k; g_Ep[cnt] = expf(bb * x); g_Em[cnt] = expf(-bb * x); }
            else      { g_pidx_i[cnt] = k; g_Ip[cnt] = expf(bb * x); g_Im[cnt] = expf(-bb * x); }
        }
    } else if (b < 704) {                // split positions
        bool is_e = (b < 584);
        const float* arr = is_e ? enh : inh;
        int j = ((b - (is_e ? 464 : 584)) * 8 + wid);
        float tj = ident[NI + j];
        int cnt = 0;
        for (int k2 = lane; k2 < NR; k2 += 32) cnt += (arr[128 + k2] <= tj);
        #pragma unroll
        for (int o = 16; o; o >>= 1) cnt += __shfl_xor_sync(FULL, cnt, o);
        if (lane == 0) { if (is_e) g_pos_e[j] = cnt; else g_pos_i[j] = cnt; }
    } else if (b < 824) {                // ctop
        int j = (b - 704) * 8 + wid;
        float tj = ident[NI + j];
        float c = 0.0f;
        for (int k = lane; k < NI; k += 32)
            c += expf(-bb * fabsf(enh[k] - tj)) - expf(-bb * fabsf(inh[k] - tj));
        #pragma unroll
        for (int o = 16; o; o >>= 1) c += __shfl_xor_sync(FULL, c, o);
        if (lane == 0) g_ctop[j] = c;
    } else {                             // Tp/Tm
        int j = (b - 824) * 256 + t;
        if (j < NC) {
            float tj = ident[NI + j];
            g_Tp[j] = expf(bb * tj);
            g_Tm[j] = expf(-bb * tj);
        }
    }
}

// =================== k_warm: 3-sync segmented scans ===================
__global__ void __launch_bounds__(1024, 1) k_warm(const float* __restrict__ delta) {
    __shared__ float rA[NC], rB[NC];
    __shared__ __align__(16) float SPe[NR], SQe[NR], SPi[NR], SQi[NR];
    __shared__ float2 wt2[16];
    __shared__ __align__(16) float wsum[32];
    const int t = threadIdx.x, lane = t & 31, warp = t >> 5;

    const bool role_e = (t < 224);
    const bool role_i = (t >= 256 && t < 480);
    const bool scanner = role_e || role_i;
    const int seg = role_e ? t : (t - 256);
    const int w0  = role_e ? 0 : 8;

    int4 px = make_int4(0, 0, 0, 0);
    float4 Pp = make_float4(0, 0, 0, 0), Pm = Pp;
    if (role_e) {
        px = ((const int4*)g_pidx_e)[seg];
        Pp = ((const float4*)g_Ep)[seg];
        Pm = ((const float4*)g_Em)[seg];
    } else if (role_i) {
        px = ((const int4*)g_pidx_i)[seg];
        Pp = ((const float4*)g_Ip)[seg];
        Pm = ((const float4*)g_Im)[seg];
    }
    px.x += 64; px.y += 64; px.z += 64; px.w += 64;

    float Tp = 0, Tm = 0, ct = 0; int poe = 0, poi = 0;
    if (t < NC) { Tp = g_Tp[t]; Tm = g_Tm[t]; ct = g_ctop[t];
                  poe = g_pos_e[t]; poi = g_pos_i[t];
                  rA[t] = 1.0f / (float)NTOT; }
    float s = 1.0f;
    const float d = delta[0];
    __syncthreads();
    float *rc = rA, *rn = rB;

    for (int it = 0; it <= WARM; it++) {
        float inv = (s > 0.0f) ? 1.0f / s : 1.0f;

        float sP[4], sQ[4], eP = 0, eQ = 0;
        if (scanner) {
            float r0 = rc[px.x], r1 = rc[px.y], r2 = rc[px.z], r3 = rc[px.w];
            sP[0] = r0 * Pp.x;          sQ[0] = r0 * Pm.x;
            sP[1] = sP[0] + r1 * Pp.y;  sQ[1] = sQ[0] + r1 * Pm.y;
            sP[2] = sP[1] + r2 * Pp.z;  sQ[2] = sQ[1] + r2 * Pm.z;
            sP[3] = sP[2] + r3 * Pp.w;  sQ[3] = sQ[2] + r3 * Pm.w;
            float iP = sP[3], iQ = sQ[3];
            #pragma unroll
            for (int o = 1; o < 32; o <<= 1) {
                float bP = __shfl_up_sync(FULL, iP, o);
                float bQ = __shfl_up_sync(FULL, iQ, o);
                if (lane >= o) { iP += bP; iQ += bQ; }
            }
            eP = iP - sP[3];  eQ = iQ - sQ[3];
            if (lane == 31) wt2[warp] = make_float2(iP, iQ);
        }
        __syncthreads();                                   // (1)

        if (scanner) {
            int wl = warp - w0;
            float bP = eP, bQ = eQ;
            #pragma unroll 6
            for (int w = 0; w < wl; w++) { float2 v = wt2[w0 + w]; bP += v.x; bQ += v.y; }
            float* SP = role_e ? SPe : SPi;
            float* SQ = role_e ? SQe : SQi;
            ((float4*)SP)[seg] = make_float4(bP + sP[0], bP + sP[1], bP + sP[2], bP + sP[3]);
            ((float4*)SQ)[seg] = make_float4(bQ + sQ[0], bQ + sQ[1], bQ + sQ[2], bQ + sQ[3]);
        }
        __syncthreads();                                   // (2)

        float nv = 0.0f;
        if (t < NC) {
            float tot1 = 0.0f, tot3 = 0.0f;
            #pragma unroll
            for (int w = 0; w < 7; w++) { tot1 += wt2[w].y; tot3 += wt2[8 + w].y; }
            float spe = poe ? SPe[poe - 1] : 0.0f;
            float sqe = poe ? SQe[poe - 1] : 0.0f;
            float spi = poi ? SPi[poi - 1] : 0.0f;
            float sqi = poi ? SQi[poi - 1] : 0.0f;
            float de  = Tm * spe + Tp * (tot1 - sqe);
            float di  = Tm * spi + Tp * (tot3 - sqi);
            float dot = (de - di) * inv;
            float conc = rc[t] * inv;
            if (it < WARM) {
                float dc = (d / (float)NTOT) * (ct * (1.0f / (float)NTOT) + dot);
                nv = fmaxf(conc + dc, 0.0f);
                rn[t] = nv;
            } else {
                g_base[t] = conc + (d / (float)NTOT) * dot;
            }
        }
        if (it == WARM) break;

        #pragma unroll
        for (int o = 16; o; o >>= 1) nv += __shfl_xor_sync(FULL, nv, o);
        if (lane == 0) wsum[warp] = nv;
        __syncthreads();                                   // (3)

        float acc = 0.0f;
        #pragma unroll
        for (int q = 0; q < 8; q++) {
            float4 v = ((const float4*)wsum)[q];
            acc += (v.x + v.y) + (v.z + v.w);
        }
        s = acc;
        float* tmp = rc; rc = rn; rn = tmp;
    }
}

// =================== k_gemm: 512-thread, sync loads (R7 path), 16 warps =====
#define SMA_H   0
#define SMA_L   16384
#define SMB_H   32768
#define SMB_L   40960
#define SMBASE  49152              // 960 floats
#define SMRSUM  (SMBASE + 3840)    // 128 rows x 2 col-halves
#define SMTOT   (SMRSUM + 1024)

__global__ void __launch_bounds__(512)
k_gemm(const float* __restrict__ X, const float* __restrict__ delta,
       float* __restrict__ out) {
    extern __shared__ char sm[];
    const uint32_t sb = smem_u32(sm);
    float* sbase = (float*)(sm + SMBASE);
    float* srsum = (float*)(sm + SMRSUM);
    const int tid = threadIdx.x, wid = tid >> 5, lane = tid & 31;
    const int gr = lane >> 2, tg = lane & 3;
    const int r0 = blockIdx.x * 128;
    const int rg = wid >> 1;            // row group 0..7 -> rows rg*16..+16
    const int cg = wid & 1;             // column half: cols cg*32..+32
    const int m0 = rg * 16;

    for (int i = tid; i < NC; i += 512) sbase[i] = g_base[i];

    // A tile: 128x64 fp32 -> bf16 hi/lo, SW128 swizzled
    for (int i = tid; i < 4096; i += 512) {
        int m = i >> 5, c2 = i & 31;
        float2 x = *(const float2*)(X + (size_t)(r0 + m) * 64 + 2 * c2);
        __nv_bfloat162 hp = __floats2bfloat162_rn(x.x, x.y);
        float2 hf = __bfloat1622float2(hp);
        __nv_bfloat162 lp = __floats2bfloat162_rn(x.x - hf.x, x.y - hf.y);
        uint32_t off = SW128((uint32_t)(m * 128 + c2 * 4));
        *(uint32_t*)(sm + SMA_H + off) = *(uint32_t*)&hp;
        *(uint32_t*)(sm + SMA_L + off) = *(uint32_t*)&lp;
    }
    __syncthreads();

    // chunk-invariant A fragments (per warp: its 16-row group, full K)
    uint32_t ah[4][4], al[4][4];
    {
        int arow = m0 + (lane & 7) + ((lane >> 3) & 1) * 8;
        int acol = (lane >> 4) & 1;
        #pragma unroll
        for (int ks = 0; ks < 4; ks++) {
            uint32_t off = SW128((uint32_t)(arow * 128 + (ks * 2 + acol) * 16));
            LDSM_X4(ah[ks][0], ah[ks][1], ah[ks][2], ah[ks][3], sb + SMA_H + off);
            LDSM_X4(al[ks][0], al[ks][1], al[ks][2], al[ks][3], sb + SMA_L + off);
        }
    }

    const float sc = delta[0] / (float)NTOT;
    float rsLo = 0.0f, rsHi = 0.0f;
    float2 vlo[4], vhi[4];

    const int brow_off = (lane & 7) + ((lane >> 4) & 1) * 8;
    const int bcol_off = (lane >> 3) & 1;

    for (int cc = 0; cc < 15; cc++) {
        // load B chunk (hi+lo) into smem, SW128 swizzled (sync LDG, R7 style)
        #pragma unroll
        for (int q = 0; q < 2; q++) {
            int f = q * 512 + tid;                  // 1024 uint4
            int isl = f >> 9;
            int r  = (f & 511) >> 3, ch = f & 7;
            const uint4* src = isl ? (const uint4*)g_Bl : (const uint4*)g_Bh;
            uint4 v = src[(size_t)(cc * 64 + r) * 8 + ch];
            uint32_t off = SW128((uint32_t)(r * 128 + ch * 16));
            *(uint4*)(sm + (isl ? SMB_L : SMB_H) + off) = v;
        }
        __syncthreads();

        float dacc[4][4];
        #pragma unroll
        for (int nt = 0; nt < 4; nt++)
            #pragma unroll
            for (int r = 0; r < 4; r++) dacc[nt][r] = 0.0f;

        #pragma unroll
        for (int ks = 0; ks < 4; ks++) {
            #pragma unroll
            for (int npl = 0; npl < 2; npl++) {
                int np = cg * 2 + npl;              // absolute 16-col B group
                uint32_t boff = SW128((uint32_t)((np * 16 + brow_off) * 128 +
                                                 (ks * 2 + bcol_off) * 16));
                uint32_t b0, b1, b2, b3;
                LDSM_X4(b0, b1, b2, b3, sb + SMB_H + boff);
                MMA16816(dacc[npl * 2],     ah[ks], b0, b1);
                MMA16816(dacc[npl * 2 + 1], ah[ks], b2, b3);
                MMA16816(dacc[npl * 2],     al[ks], b0, b1);
                MMA16816(dacc[npl * 2 + 1], al[ks], b2, b3);
                LDSM_X4(b0, b1, b2, b3, sb + SMB_L + boff);
                MMA16816(dacc[npl * 2],     ah[ks], b0, b1);
                MMA16816(dacc[npl * 2 + 1], ah[ks], b2, b3);
            }
        }

        // epilogue: base + relu + row-sum partials (this warp's 32 cols)
        #pragma unroll
        for (int nt = 0; nt < 4; nt++) {
            float2 bb = *(const float2*)(sbase + cc * 64 + cg * 32 + nt * 8 + tg * 2);
            float v00 = fmaxf(bb.x + sc * dacc[nt][0], 0.0f);
            float v01 = fmaxf(bb.y + sc * dacc[nt][1], 0.0f);
            float v10 = fmaxf(bb.x + sc * dacc[nt][2], 0.0f);
            float v11 = fmaxf(bb.y + sc * dacc[nt][3], 0.0f);
            rsLo += v00 + v01;
            rsHi += v10 + v11;
            if (cc == 0) { vlo[nt] = make_float2(v00, v01);
                           vhi[nt] = make_float2(v10, v11); }
        }
        __syncthreads();
    }

    // combine row sums: quad-reduce, then cross-warp via smem (2 col halves)
    rsLo += __shfl_xor_sync(FULL, rsLo, 1);
    rsLo += __shfl_xor_sync(FULL, rsLo, 2);
    rsHi += __shfl_xor_sync(FULL, rsHi, 1);
    rsHi += __shfl_xor_sync(FULL, rsHi, 2);
    if (tg == 0) {
        srsum[(m0 + gr) * 2 + cg]     = rsLo;
        srsum[(m0 + gr + 8) * 2 + cg] = rsHi;
    }
    __syncthreads();

    int rowLo = m0 + gr, rowHi = rowLo + 8;
    float tLo = srsum[rowLo * 2] + srsum[rowLo * 2 + 1];
    float tHi = srsum[rowHi * 2] + srsum[rowHi * 2 + 1];
    float invLo = (tLo > 0.0f) ? 1.0f / tLo : 1.0f;
    float invHi = (tHi > 0.0f) ? 1.0f / tHi : 1.0f;

    #pragma unroll
    for (int nt = 0; nt < 4; nt++) {
        int c = cg * 32 + nt * 8 + tg * 2;
        *(float2*)(out + (size_t)(r0 + rowLo) * 64 + c) =
            make_float2(vlo[nt].x * invLo, vlo[nt].y * invLo);
        *(float2*)(out + (size_t)(r0 + rowHi) * 64 + c) =
            make_float2(vhi[nt].x * invHi, vhi[nt].y * invHi);
    }
}

// ---------------- launch ----------------
extern "C" void kernel_launch(void* const* d_in, const int* in_sizes, int n_in,
                              void* d_out, int out_size) {
    const float* inputs      = (const float*)d_in[0];
    const float* identifiers = (const float*)d_in[1];
    const float* enhancers   = (const float*)d_in[2];
    const float* inhibitors  = (const float*)d_in[3];
    const float* beta        = (const float*)d_in[4];
    const float* delta       = (const float*)d_in[5];
    (void)in_sizes; (void)n_in; (void)out_size;

    cudaFuncSetAttribute(k_gemm, cudaFuncAttributeMaxDynamicSharedMemorySize, SMTOT);

    k_init<<<828, 256>>>(identifiers, enhancers, inhibitors, beta);
    k_warm<<<1, 1024>>>(delta);
    k_gemm<<<128, 512, SMTOT>>>(inputs, delta, (float*)d_out);
}

// round 10
// speedup vs baseline: 1.0672x; 1.0672x over previous
#include <cuda_runtime.h>
#include <cuda_bf16.h>
#include <math.h>
#include <stdint.h>

#define NTOT 1024
#define NI   64
#define NC   960
#define NR   896
#define WARM 25
#define FULL 0xffffffffu

// ---------------- device scratch ----------------
__device__ __align__(16) __nv_bfloat16 g_Bh[NC * 64];
__device__ __align__(16) __nv_bfloat16 g_Bl[NC * 64];
__device__ __align__(16) float g_Ep[NR], g_Em[NR], g_Ip[NR], g_Im[NR];
__device__ __align__(16) int   g_pidx_e[NR], g_pidx_i[NR];
__device__ __align__(16) int   g_pos_e[NC], g_pos_i[NC];
__device__ __align__(16) float g_Tp[NC], g_Tm[NC], g_ctop[NC];
__device__ __align__(16) float g_base[NC];
__device__ int g_cnt;          // table-ready counter (reset by block 0 each run)

__device__ __forceinline__ uint32_t smem_u32(const void* p) {
    uint32_t a;
    asm("{ .reg .u64 t; cvta.to.shared.u64 t, %1; cvt.u32.u64 %0, t; }" : "=r"(a) : "l"(p));
    return a;
}
#define SW128(x) ((x) ^ (((x) >> 3) & 0x70))

#define LDSM_X4(r0, r1, r2, r3, a) \
    asm volatile("ldmatrix.sync.aligned.m8n8.x4.shared.b16 {%0,%1,%2,%3}, [%4];" \
        : "=r"(r0), "=r"(r1), "=r"(r2), "=r"(r3) : "r"(a))

#define MMA16816(d, a, b0, b1) \
    asm volatile("mma.sync.aligned.m16n8k16.row.col.f32.bf16.bf16.f32 " \
        "{%0,%1,%2,%3}, {%4,%5,%6,%7}, {%8,%9}, {%0,%1,%2,%3};" \
        : "+f"((d)[0]), "+f"((d)[1]), "+f"((d)[2]), "+f"((d)[3]) \
        : "r"((a)[0]), "r"((a)[1]), "r"((a)[2]), "r"((a)[3]), "r"(b0), "r"(b1))

// =================== k_prep: block0=warm, 1..60=B build, 61..120=tables =====
__global__ void __launch_bounds__(1024, 1)
k_prep(const float* __restrict__ delta, const float* __restrict__ ident,
       const float* __restrict__ enh,  const float* __restrict__ inh,
       const float* __restrict__ beta) {
    const int b = blockIdx.x, t = threadIdx.x;
    const int lane = t & 31, wid = t >> 5;

    if (b >= 1 && b <= 60) {             // ---- B matrix build (R8-proven) ----
        const float bb = beta[0];
        int idx = (b - 1) * 1024 + t;    // 60*1024 = 61440 exactly
        int j = idx >> 6, k = idx & 63;
        float id = ident[NI + j];
        float v = expf(-bb * fabsf(enh[k] - id)) - expf(-bb * fabsf(inh[k] - id));
        __nv_bfloat16 h = __float2bfloat16(v);
        __nv_bfloat16 l = __float2bfloat16(v - __bfloat162float(h));
        g_Bh[idx] = h;
        g_Bl[idx] = l;
        return;
    }

    if (b >= 61) {                       // ---- small tables, then signal ----
        const float bb = beta[0];
        const int b2 = b - 61;           // 0..59
        // Phase A: ranks + permuted exp tables (warp per element)
        {
            int W = b2 * 32 + wid;       // 0..1919
            if (W < 2 * NR) {
                bool is_e = (W < NR);
                const float* arr = is_e ? enh : inh;
                int k = is_e ? W : (W - NR);
                float x = arr[128 + k];
                int cnt = 0;
                for (int k2 = lane; k2 < NR; k2 += 32) {
                    float y = arr[128 + k2];
                    cnt += (y < x) || (y == x && k2 < k);
                }
                #pragma unroll
                for (int o = 16; o; o >>= 1) cnt += __shfl_xor_sync(FULL, cnt, o);
                if (lane == 0) {
                    if (is_e) { g_pidx_e[cnt] = k; g_Ep[cnt] = expf(bb * x); g_Em[cnt] = expf(-bb * x); }
                    else      { g_pidx_i[cnt] = k; g_Ip[cnt] = expf(bb * x); g_Im[cnt] = expf(-bb * x); }
                }
            }
        }
        // Phase B: per-column tables. 16 j per block, 2 warps per j.
        {
            int j = b2 * 16 + (wid >> 1);
            int half = wid & 1;
            float tj = ident[NI + j];
            if (half == 0) {
                int cnt = 0;
                for (int k2 = lane; k2 < NR; k2 += 32) cnt += (enh[128 + k2] <= tj);
                #pragma unroll
                for (int o = 16; o; o >>= 1) cnt += __shfl_xor_sync(FULL, cnt, o);
                if (lane == 0) {
                    g_pos_e[j] = cnt;
                    g_Tp[j] = expf(bb * tj);
                    g_Tm[j] = expf(-bb * tj);
                }
            } else {
                int cnt = 0;
                for (int k2 = lane; k2 < NR; k2 += 32) cnt += (inh[128 + k2] <= tj);
                float c = 0.0f;
                for (int k = lane; k < NI; k += 32)
                    c += expf(-bb * fabsf(enh[k] - tj)) - expf(-bb * fabsf(inh[k] - tj));
                #pragma unroll
                for (int o = 16; o; o >>= 1) {
                    cnt += __shfl_xor_sync(FULL, cnt, o);
                    c   += __shfl_xor_sync(FULL, c, o);
                }
                if (lane == 0) { g_pos_i[j] = cnt; g_ctop[j] = c; }
            }
        }
        __syncthreads();
        if (t == 0) {
            __threadfence();
            atomicAdd(&g_cnt, 1);
        }
        return;
    }

    // ================= block 0: wait for tables, then R7 warm body =========
    if (t == 0) {
        int v;
        do {
            asm volatile("ld.acquire.gpu.s32 %0, [%1];" : "=r"(v) : "l"(&g_cnt) : "memory");
        } while (v < 60);
        g_cnt = 0;                       // reset for next graph replay
    }
    __syncthreads();

    __shared__ float rA[NC], rB[NC];
    __shared__ __align__(16) float SPe[NR], SQe[NR], SPi[NR], SQi[NR];
    __shared__ float2 wt2[16];
    __shared__ float wsum[32];
    __shared__ float tot1, tot3, s_sh;

    const bool role_e = (t < 224);
    const bool role_i = (t >= 256 && t < 480);
    const bool scanner = role_e || role_i;
    const int seg = role_e ? t : (t - 256);
    const int w0  = role_e ? 0 : 8;

    int4 px = make_int4(0, 0, 0, 0);
    float4 Pp = make_float4(0, 0, 0, 0), Pm = Pp;
    if (role_e) {
        px = ((const int4*)g_pidx_e)[seg];
        Pp = ((const float4*)g_Ep)[seg];
        Pm = ((const float4*)g_Em)[seg];
    } else if (role_i) {
        px = ((const int4*)g_pidx_i)[seg];
        Pp = ((const float4*)g_Ip)[seg];
        Pm = ((const float4*)g_Im)[seg];
    }
    px.x += 64; px.y += 64; px.z += 64; px.w += 64;

    float Tp = 0, Tm = 0, ct = 0; int poe = 0, poi = 0;
    if (t < NC) { Tp = g_Tp[t]; Tm = g_Tm[t]; ct = g_ctop[t];
                  poe = g_pos_e[t]; poi = g_pos_i[t];
                  rA[t] = 1.0f / (float)NTOT; }
    float s = 1.0f;
    const float d = delta[0];
    __syncthreads();
    float *rc = rA, *rn = rB;
    const int warp = wid;

    for (int it = 0; it <= WARM; it++) {
        float inv = (s > 0.0f) ? 1.0f / s : 1.0f;

        float sP[4], sQ[4], eP = 0, eQ = 0;
        if (scanner) {
            float r0 = rc[px.x], r1 = rc[px.y], r2 = rc[px.z], r3 = rc[px.w];
            sP[0] = r0 * Pp.x;          sQ[0] = r0 * Pm.x;
            sP[1] = sP[0] + r1 * Pp.y;  sQ[1] = sQ[0] + r1 * Pm.y;
            sP[2] = sP[1] + r2 * Pp.z;  sQ[2] = sQ[1] + r2 * Pm.z;
            sP[3] = sP[2] + r3 * Pp.w;  sQ[3] = sQ[2] + r3 * Pm.w;
            float iP = sP[3], iQ = sQ[3];
            #pragma unroll
            for (int o = 1; o < 32; o <<= 1) {
                float bP = __shfl_up_sync(FULL, iP, o);
                float bQ = __shfl_up_sync(FULL, iQ, o);
                if (lane >= o) { iP += bP; iQ += bQ; }
            }
            eP = iP - sP[3];  eQ = iQ - sQ[3];
            if (lane == 31) wt2[warp] = make_float2(iP, iQ);
        }
        __syncthreads();                                   // (1)

        if (scanner) {
            int wl = warp - w0;
            float bP = eP, bQ = eQ;
            #pragma unroll 6
            for (int w = 0; w < wl; w++) { float2 v = wt2[w0 + w]; bP += v.x; bQ += v.y; }
            float* SP = role_e ? SPe : SPi;
            float* SQ = role_e ? SQe : SQi;
            ((float4*)SP)[seg] = make_float4(bP + sP[0], bP + sP[1], bP + sP[2], bP + sP[3]);
            ((float4*)SQ)[seg] = make_float4(bQ + sQ[0], bQ + sQ[1], bQ + sQ[2], bQ + sQ[3]);
        }
        if (t == 0 || t == 256) {
            float tot = 0.0f;
            #pragma unroll
            for (int w = 0; w < 7; w++) tot += wt2[w0 + w].y;
            if (t == 0) tot1 = tot; else tot3 = tot;
        }
        __syncthreads();                                   // (2)

        float nv = 0.0f;
        if (t < NC) {
            float spe = poe ? SPe[poe - 1] : 0.0f;
            float sqe = poe ? SQe[poe - 1] : 0.0f;
            float spi = poi ? SPi[poi - 1] : 0.0f;
            float sqi = poi ? SQi[poi - 1] : 0.0f;
            float de  = Tm * spe + Tp * (tot1 - sqe);
            float di  = Tm * spi + Tp * (tot3 - sqi);
            float dot = (de - di) * inv;
            float conc = rc[t] * inv;
            if (it < WARM) {
                float dc = (d / (float)NTOT) * (ct * (1.0f / (float)NTOT) + dot);
                nv = fmaxf(conc + dc, 0.0f);
                rn[t] = nv;
            } else {
                g_base[t] = conc + (d / (float)NTOT) * dot;
            }
        }
        if (it == WARM) break;

        #pragma unroll
        for (int o = 16; o; o >>= 1) nv += __shfl_xor_sync(FULL, nv, o);
        if (lane == 0) wsum[warp] = nv;
        __syncthreads();                                   // (3)
        if (warp == 0) {
            float v = wsum[lane];
            #pragma unroll
            for (int o = 16; o; o >>= 1) v += __shfl_xor_sync(FULL, v, o);
            if (lane == 0) s_sh = v;
        }
        __syncthreads();                                   // (4)
        s = s_sh;
        float* tmp = rc; rc = rn; rn = tmp;
    }
}

// =================== k_gemm: R7-exact mma.sync bf16-split GEMM ==============
#define SMA_H  0
#define SMA_L  16384
#define SMB_H  32768
#define SMB_L  40960
#define SMBASE 49152
#define SMTOT  (SMBASE + 3840)

__global__ void __launch_bounds__(256)
k_gemm(const float* __restrict__ X, const float* __restrict__ delta,
       float* __restrict__ out) {
    extern __shared__ char sm[];
    const uint32_t sb = smem_u32(sm);
    float* sbase = (float*)(sm + SMBASE);
    const int tid = threadIdx.x, wid = tid >> 5, lane = tid & 31;
    const int gr = lane >> 2, tg = lane & 3;
    const int r0 = blockIdx.x * 128;
    const int m0 = wid * 16;

    for (int i = tid; i < NC; i += 256) sbase[i] = g_base[i];

    for (int i = tid; i < 4096; i += 256) {
        int m = i >> 5, c2 = i & 31;
        float2 x = *(const float2*)(X + (size_t)(r0 + m) * 64 + 2 * c2);
        __nv_bfloat162 hp = __floats2bfloat162_rn(x.x, x.y);
        float2 hf = __bfloat1622float2(hp);
        __nv_bfloat162 lp = __floats2bfloat162_rn(x.x - hf.x, x.y - hf.y);
        uint32_t off = SW128((uint32_t)(m * 128 + c2 * 4));
        *(uint32_t*)(sm + SMA_H + off) = *(uint32_t*)&hp;
        *(uint32_t*)(sm + SMA_L + off) = *(uint32_t*)&lp;
    }
    __syncthreads();

    uint32_t ah[4][4], al[4][4];
    {
        int arow = m0 + (lane & 7) + ((lane >> 3) & 1) * 8;
        int acol = (lane >> 4) & 1;
        #pragma unroll
        for (int ks = 0; ks < 4; ks++) {
            uint32_t off = SW128((uint32_t)(arow * 128 + (ks * 2 + acol) * 16));
            LDSM_X4(ah[ks][0], ah[ks][1], ah[ks][2], ah[ks][3], sb + SMA_H + off);
            LDSM_X4(al[ks][0], al[ks][1], al[ks][2], al[ks][3], sb + SMA_L + off);
        }
    }

    const float sc = delta[0] / (float)NTOT;
    float rsLo = 0.0f, rsHi = 0.0f;
    float2 vlo[8], vhi[8];

    const int brow_off = (lane & 7) + ((lane >> 4) & 1) * 8;
    const int bcol_off = (lane >> 3) & 1;

    for (int cc = 0; cc < 15; cc++) {
        #pragma unroll
        for (int q = 0; q < 4; q++) {
            int f = q * 256 + tid;
            int isl = f >> 9;
            int r  = (f & 511) >> 3, ch = f & 7;
            const uint4* src = isl ? (const uint4*)g_Bl : (const uint4*)g_Bh;
            uint4 v = src[(size_t)(cc * 64 + r) * 8 + ch];
            uint32_t off = SW128((uint32_t)(r * 128 + ch * 16));
            *(uint4*)(sm + (isl ? SMB_L : SMB_H) + off) = v;
        }
        __syncthreads();

        float dacc[8][4];
        #pragma unroll
        for (int nt = 0; nt < 8; nt++)
            #pragma unroll
            for (int r = 0; r < 4; r++) dacc[nt][r] = 0.0f;

        #pragma unroll
        for (int ks = 0; ks < 4; ks++) {
            #pragma unroll
            for (int np = 0; np < 4; np++) {
                uint32_t boff = SW128((uint32_t)((np * 16 + brow_off) * 128 +
                                                 (ks * 2 + bcol_off) * 16));
                uint32_t b0, b1, b2, b3;
                LDSM_X4(b0, b1, b2, b3, sb + SMB_H + boff);
                MMA16816(dacc[np * 2],     ah[ks], b0, b1);
                MMA16816(dacc[np * 2 + 1], ah[ks], b2, b3);
                MMA16816(dacc[np * 2],     al[ks], b0, b1);
                MMA16816(dacc[np * 2 + 1], al[ks], b2, b3);
                LDSM_X4(b0, b1, b2, b3, sb + SMB_L + boff);
                MMA16816(dacc[np * 2],     ah[ks], b0, b1);
                MMA16816(dacc[np * 2 + 1], ah[ks], b2, b3);
            }
        }

        #pragma unroll
        for (int nt = 0; nt < 8; nt++) {
            float2 bb = *(const float2*)(sbase + cc * 64 + nt * 8 + tg * 2);
            float v00 = fmaxf(bb.x + sc * dacc[nt][0], 0.0f);
            float v01 = fmaxf(bb.y + sc * dacc[nt][1], 0.0f);
            float v10 = fmaxf(bb.x + sc * dacc[nt][2], 0.0f);
            float v11 = fmaxf(bb.y + sc * dacc[nt][3], 0.0f);
            rsLo += v00 + v01;
            rsHi += v10 + v11;
            if (cc == 0) { vlo[nt] = make_float2(v00, v01);
                           vhi[nt] = make_float2(v10, v11); }
        }
        __syncthreads();
    }

    rsLo += __shfl_xor_sync(FULL, rsLo, 1);
    rsLo += __shfl_xor_sync(FULL, rsLo, 2);
    rsHi += __shfl_xor_sync(FULL, rsHi, 1);
    rsHi += __shfl_xor_sync(FULL, rsHi, 2);
    float invLo = (rsLo > 0.0f) ? 1.0f / rsLo : 1.0f;
    float invHi = (rsHi > 0.0f) ? 1.0f / rsHi : 1.0f;

    int rowLo = r0 + m0 + gr, rowHi = rowLo + 8;
    #pragma unroll
    for (int nt = 0; nt < 8; nt++) {
        int c = nt * 8 + tg * 2;
        *(float2*)(out + (size_t)rowLo * 64 + c) =
            make_float2(vlo[nt].x * invLo, vlo[nt].y * invLo);
        *(float2*)(out + (size_t)rowHi * 64 + c) =
            make_float2(vhi[nt].x * invHi, vhi[nt].y * invHi);
    }
}

// ---------------- launch ----------------
extern "C" void kernel_launch(void* const* d_in, const int* in_sizes, int n_in,
                              void* d_out, int out_size) {
    const float* inputs      = (const float*)d_in[0];
    const float* identifiers = (const float*)d_in[1];
    const float* enhancers   = (const float*)d_in[2];
    const float* inhibitors  = (const float*)d_in[3];
    const float* beta        = (const float*)d_in[4];
    const float* delta       = (const float*)d_in[5];
    (void)in_sizes; (void)n_in; (void)out_size;

    cudaFuncSetAttribute(k_gemm, cudaFuncAttributeMaxDynamicSharedMemorySize, SMTOT);

    k_prep<<<121, 1024>>>(delta, identifiers, enhancers, inhibitors, beta);
    k_gemm<<<128, 256, SMTOT>>>(inputs, delta, (float*)d_out);
}

// round 11
// speedup vs baseline: 1.1804x; 1.1061x over previous
#include <cuda_runtime.h>
#include <cuda_bf16.h>
#include <math.h>
#include <stdint.h>

#define NTOT 1024
#define NI   64
#define NC   960
#define NR   896
#define WARM 25
#define FULL 0xffffffffu

// ---------------- device scratch ----------------
__device__ __align__(16) __nv_bfloat16 g_Bh[NC * 64];
__device__ __align__(16) __nv_bfloat16 g_Bl[NC * 64];
__device__ __align__(16) float g_Ep[NR], g_Em[NR], g_Ip[NR], g_Im[NR];
__device__ __align__(16) int   g_pidx_e[NR], g_pidx_i[NR];
__device__ __align__(16) int   g_pos_e[NC], g_pos_i[NC];
__device__ __align__(16) float g_Tp[NC], g_Tm[NC], g_ctop[NC];
__device__ __align__(16) float g_base[NC];

__device__ __forceinline__ uint32_t smem_u32(const void* p) {
    uint32_t a;
    asm("{ .reg .u64 t; cvta.to.shared.u64 t, %1; cvt.u32.u64 %0, t; }" : "=r"(a) : "l"(p));
    return a;
}
#define SW128(x) ((x) ^ (((x) >> 3) & 0x70))

#define LDSM_X4(r0, r1, r2, r3, a) \
    asm volatile("ldmatrix.sync.aligned.m8n8.x4.shared.b16 {%0,%1,%2,%3}, [%4];" \
        : "=r"(r0), "=r"(r1), "=r"(r2), "=r"(r3) : "r"(a))

#define MMA16816(d, a, b0, b1) \
    asm volatile("mma.sync.aligned.m16n8k16.row.col.f32.bf16.bf16.f32 " \
        "{%0,%1,%2,%3}, {%4,%5,%6,%7}, {%8,%9}, {%0,%1,%2,%3};" \
        : "+f"((d)[0]), "+f"((d)[1]), "+f"((d)[2]), "+f"((d)[3]) \
        : "r"((a)[0]), "r"((a)[1]), "r"((a)[2]), "r"((a)[3]), "r"(b0), "r"(b1))

// =================== k_init: R7-exact ===================
__global__ void k_init(const float* __restrict__ ident, const float* __restrict__ enh,
                       const float* __restrict__ inh,  const float* __restrict__ beta) {
    const int b = blockIdx.x, t = threadIdx.x;
    const int wid = t >> 5, lane = t & 31;
    const float bb = beta[0];

    if (b < 240) {
        int idx = b * 256 + t;
        int j = idx >> 6, k = idx & 63;
        float id = ident[NI + j];
        float v = expf(-bb * fabsf(enh[k] - id)) - expf(-bb * fabsf(inh[k] - id));
        __nv_bfloat16 h = __float2bfloat16(v);
        __nv_bfloat16 l = __float2bfloat16(v - __bfloat162float(h));
        g_Bh[idx] = h;
        g_Bl[idx] = l;
    } else if (b < 464) {
        bool is_e = (b < 352);
        const float* arr = is_e ? enh : inh;
        int k = ((b - (is_e ? 240 : 352)) * 8 + wid);
        float x = arr[128 + k];
        int cnt = 0;
        for (int k2 = lane; k2 < NR; k2 += 32) {
            float y = arr[128 + k2];
            cnt += (y < x) || (y == x && k2 < k);
        }
        #pragma unroll
        for (int o = 16; o; o >>= 1) cnt += __shfl_xor_sync(FULL, cnt, o);
        if (lane == 0) {
            if (is_e) { g_pidx_e[cnt] = k; g_Ep[cnt] = expf(bb * x); g_Em[cnt] = expf(-bb * x); }
            else      { g_pidx_i[cnt] = k; g_Ip[cnt] = expf(bb * x); g_Im[cnt] = expf(-bb * x); }
        }
    } else if (b < 704) {
        bool is_e = (b < 584);
        const float* arr = is_e ? enh : inh;
        int j = ((b - (is_e ? 464 : 584)) * 8 + wid);
        float tj = ident[NI + j];
        int cnt = 0;
        for (int k2 = lane; k2 < NR; k2 += 32) cnt += (arr[128 + k2] <= tj);
        #pragma unroll
        for (int o = 16; o; o >>= 1) cnt += __shfl_xor_sync(FULL, cnt, o);
        if (lane == 0) { if (is_e) g_pos_e[j] = cnt; else g_pos_i[j] = cnt; }
    } else if (b < 824) {
        int j = (b - 704) * 8 + wid;
        float tj = ident[NI + j];
        float c = 0.0f;
        for (int k = lane; k < NI; k += 32)
            c += expf(-bb * fabsf(enh[k] - tj)) - expf(-bb * fabsf(inh[k] - tj));
        #pragma unroll
        for (int o = 16; o; o >>= 1) c += __shfl_xor_sync(FULL, c, o);
        if (lane == 0) g_ctop[j] = c;
    } else {
        int j = (b - 824) * 256 + t;
        if (j < NC) {
            float tj = ident[NI + j];
            g_Tp[j] = expf(bb * tj);
            g_Tm[j] = expf(-bb * tj);
        }
    }
}

// =================== k_warm: R7-exact ===================
__global__ void __launch_bounds__(1024, 1) k_warm(const float* __restrict__ delta) {
    __shared__ float rA[NC], rB[NC];
    __shared__ __align__(16) float SPe[NR], SQe[NR], SPi[NR], SQi[NR];
    __shared__ float2 wt2[16];
    __shared__ float wsum[32];
    __shared__ float tot1, tot3, s_sh;
    const int t = threadIdx.x, lane = t & 31, warp = t >> 5;

    const bool role_e = (t < 224);
    const bool role_i = (t >= 256 && t < 480);
    const bool scanner = role_e || role_i;
    const int seg = role_e ? t : (t - 256);
    const int w0  = role_e ? 0 : 8;

    int4 px = make_int4(0, 0, 0, 0);
    float4 Pp = make_float4(0, 0, 0, 0), Pm = Pp;
    if (role_e) {
        px = ((const int4*)g_pidx_e)[seg];
        Pp = ((const float4*)g_Ep)[seg];
        Pm = ((const float4*)g_Em)[seg];
    } else if (role_i) {
        px = ((const int4*)g_pidx_i)[seg];
        Pp = ((const float4*)g_Ip)[seg];
        Pm = ((const float4*)g_Im)[seg];
    }
    px.x += 64; px.y += 64; px.z += 64; px.w += 64;

    float Tp = 0, Tm = 0, ct = 0; int poe = 0, poi = 0;
    if (t < NC) { Tp = g_Tp[t]; Tm = g_Tm[t]; ct = g_ctop[t];
                  poe = g_pos_e[t]; poi = g_pos_i[t];
                  rA[t] = 1.0f / (float)NTOT; }
    float s = 1.0f;
    const float d = delta[0];
    __syncthreads();
    float *rc = rA, *rn = rB;

    for (int it = 0; it <= WARM; it++) {
        float inv = (s > 0.0f) ? 1.0f / s : 1.0f;

        float sP[4], sQ[4], eP = 0, eQ = 0;
        if (scanner) {
            float r0 = rc[px.x], r1 = rc[px.y], r2 = rc[px.z], r3 = rc[px.w];
            sP[0] = r0 * Pp.x;          sQ[0] = r0 * Pm.x;
            sP[1] = sP[0] + r1 * Pp.y;  sQ[1] = sQ[0] + r1 * Pm.y;
            sP[2] = sP[1] + r2 * Pp.z;  sQ[2] = sQ[1] + r2 * Pm.z;
            sP[3] = sP[2] + r3 * Pp.w;  sQ[3] = sQ[2] + r3 * Pm.w;
            float iP = sP[3], iQ = sQ[3];
            #pragma unroll
            for (int o = 1; o < 32; o <<= 1) {
                float bP = __shfl_up_sync(FULL, iP, o);
                float bQ = __shfl_up_sync(FULL, iQ, o);
                if (lane >= o) { iP += bP; iQ += bQ; }
            }
            eP = iP - sP[3];  eQ = iQ - sQ[3];
            if (lane == 31) wt2[warp] = make_float2(iP, iQ);
        }
        __syncthreads();

        if (scanner) {
            int wl = warp - w0;
            float bP = eP, bQ = eQ;
            #pragma unroll 6
            for (int w = 0; w < wl; w++) { float2 v = wt2[w0 + w]; bP += v.x; bQ += v.y; }
            float* SP = role_e ? SPe : SPi;
            float* SQ = role_e ? SQe : SQi;
            ((float4*)SP)[seg] = make_float4(bP + sP[0], bP + sP[1], bP + sP[2], bP + sP[3]);
            ((float4*)SQ)[seg] = make_float4(bQ + sQ[0], bQ + sQ[1], bQ + sQ[2], bQ + sQ[3]);
        }
        if (t == 0 || t == 256) {
            float tot = 0.0f;
            #pragma unroll
            for (int w = 0; w < 7; w++) tot += wt2[w0 + w].y;
            if (t == 0) tot1 = tot; else tot3 = tot;
        }
        __syncthreads();

        float nv = 0.0f;
        if (t < NC) {
            float spe = poe ? SPe[poe - 1] : 0.0f;
            float sqe = poe ? SQe[poe - 1] : 0.0f;
            float spi = poi ? SPi[poi - 1] : 0.0f;
            float sqi = poi ? SQi[poi - 1] : 0.0f;
            float de  = Tm * spe + Tp * (tot1 - sqe);
            float di  = Tm * spi + Tp * (tot3 - sqi);
            float dot = (de - di) * inv;
            float conc = rc[t] * inv;
            if (it < WARM) {
                float dc = (d / (float)NTOT) * (ct * (1.0f / (float)NTOT) + dot);
                nv = fmaxf(conc + dc, 0.0f);
                rn[t] = nv;
            } else {
                g_base[t] = conc + (d / (float)NTOT) * dot;
            }
        }
        if (it == WARM) break;

        #pragma unroll
        for (int o = 16; o; o >>= 1) nv += __shfl_xor_sync(FULL, nv, o);
        if (lane == 0) wsum[warp] = nv;
        __syncthreads();
        if (warp == 0) {
            float v = wsum[lane];
            #pragma unroll
            for (int o = 16; o; o >>= 1) v += __shfl_xor_sync(FULL, v, o);
            if (lane == 0) s_sh = v;
        }
        __syncthreads();
        s = s_sh;
        float* tmp = rc; rc = rn; rn = tmp;
    }
}

// =================== k_gemm: 64-row tiles, 2 CTAs/SM ===================
#define SMA_H   0                  // 64 rows x 128B
#define SMA_L   8192
#define SMB_H   16384              // 64 rows x 128B
#define SMB_L   24576
#define SMBASE  32768              // 960 floats
#define SMRSUM  (SMBASE + 3840)    // 64 rows x 2 halves
#define SMTOT   (SMRSUM + 512)

__global__ void __launch_bounds__(256, 2)
k_gemm(const float* __restrict__ X, const float* __restrict__ delta,
       float* __restrict__ out) {
    extern __shared__ char sm[];
    const uint32_t sb = smem_u32(sm);
    float* sbase = (float*)(sm + SMBASE);
    float* srsum = (float*)(sm + SMRSUM);
    const int tid = threadIdx.x, wid = tid >> 5, lane = tid & 31;
    const int gr = lane >> 2, tg = lane & 3;
    const int r0 = blockIdx.x * 64;
    const int rg = wid >> 1;            // 0..3 -> rows rg*16..+16
    const int cg = wid & 1;             // col half: cg*32..+32
    const int m0 = rg * 16;

    for (int i = tid; i < NC; i += 256) sbase[i] = g_base[i];

    // A tile: 64x64 fp32 -> bf16 hi/lo, SW128 swizzled (2048 float2)
    for (int i = tid; i < 2048; i += 256) {
        int m = i >> 5, c2 = i & 31;
        float2 x = *(const float2*)(X + (size_t)(r0 + m) * 64 + 2 * c2);
        __nv_bfloat162 hp = __floats2bfloat162_rn(x.x, x.y);
        float2 hf = __bfloat1622float2(hp);
        __nv_bfloat162 lp = __floats2bfloat162_rn(x.x - hf.x, x.y - hf.y);
        uint32_t off = SW128((uint32_t)(m * 128 + c2 * 4));
        *(uint32_t*)(sm + SMA_H + off) = *(uint32_t*)&hp;
        *(uint32_t*)(sm + SMA_L + off) = *(uint32_t*)&lp;
    }
    __syncthreads();

    // chunk-invariant A fragments (per warp: its 16-row group, full K)
    uint32_t ah[4][4], al[4][4];
    {
        int arow = m0 + (lane & 7) + ((lane >> 3) & 1) * 8;
        int acol = (lane >> 4) & 1;
        #pragma unroll
        for (int ks = 0; ks < 4; ks++) {
            uint32_t off = SW128((uint32_t)(arow * 128 + (ks * 2 + acol) * 16));
            LDSM_X4(ah[ks][0], ah[ks][1], ah[ks][2], ah[ks][3], sb + SMA_H + off);
            LDSM_X4(al[ks][0], al[ks][1], al[ks][2], al[ks][3], sb + SMA_L + off);
        }
    }

    const float sc = delta[0] / (float)NTOT;
    float rsLo = 0.0f, rsHi = 0.0f;
    float2 vlo[4], vhi[4];

    const int brow_off = (lane & 7) + ((lane >> 4) & 1) * 8;
    const int bcol_off = (lane >> 3) & 1;

    for (int cc = 0; cc < 15; cc++) {
        // load B chunk (hi+lo): 1024 uint4 over 256 threads
        #pragma unroll
        for (int q = 0; q < 4; q++) {
            int f = q * 256 + tid;
            int isl = f >> 9;
            int r  = (f & 511) >> 3, ch = f & 7;
            const uint4* src = isl ? (const uint4*)g_Bl : (const uint4*)g_Bh;
            uint4 v = src[(size_t)(cc * 64 + r) * 8 + ch];
            uint32_t off = SW128((uint32_t)(r * 128 + ch * 16));
            *(uint4*)(sm + (isl ? SMB_L : SMB_H) + off) = v;
        }
        __syncthreads();

        float dacc[4][4];
        #pragma unroll
        for (int nt = 0; nt < 4; nt++)
            #pragma unroll
            for (int r = 0; r < 4; r++) dacc[nt][r] = 0.0f;

        #pragma unroll
        for (int ks = 0; ks < 4; ks++) {
            #pragma unroll
            for (int npl = 0; npl < 2; npl++) {
                int np = cg * 2 + npl;
                uint32_t boff = SW128((uint32_t)((np * 16 + brow_off) * 128 +
                                                 (ks * 2 + bcol_off) * 16));
                uint32_t b0, b1, b2, b3;
                LDSM_X4(b0, b1, b2, b3, sb + SMB_H + boff);
                MMA16816(dacc[npl * 2],     ah[ks], b0, b1);
                MMA16816(dacc[npl * 2 + 1], ah[ks], b2, b3);
                MMA16816(dacc[npl * 2],     al[ks], b0, b1);
                MMA16816(dacc[npl * 2 + 1], al[ks], b2, b3);
                LDSM_X4(b0, b1, b2, b3, sb + SMB_L + boff);
                MMA16816(dacc[npl * 2],     ah[ks], b0, b1);
                MMA16816(dacc[npl * 2 + 1], ah[ks], b2, b3);
            }
        }

        // epilogue: base + relu + row-sum partials (this warp's 32 cols)
        #pragma unroll
        for (int nt = 0; nt < 4; nt++) {
            float2 bb = *(const float2*)(sbase + cc * 64 + cg * 32 + nt * 8 + tg * 2);
            float v00 = fmaxf(bb.x + sc * dacc[nt][0], 0.0f);
            float v01 = fmaxf(bb.y + sc * dacc[nt][1], 0.0f);
            float v10 = fmaxf(bb.x + sc * dacc[nt][2], 0.0f);
            float v11 = fmaxf(bb.y + sc * dacc[nt][3], 0.0f);
            rsLo += v00 + v01;
            rsHi += v10 + v11;
            if (cc == 0) { vlo[nt] = make_float2(v00, v01);
                           vhi[nt] = make_float2(v10, v11); }
        }
        __syncthreads();
    }

    // row sums: quad-reduce, cross-warp combine of the 2 col halves
    rsLo += __shfl_xor_sync(FULL, rsLo, 1);
    rsLo += __shfl_xor_sync(FULL, rsLo, 2);
    rsHi += __shfl_xor_sync(FULL, rsHi, 1);
    rsHi += __shfl_xor_sync(FULL, rsHi, 2);
    if (tg == 0) {
        srsum[(m0 + gr) * 2 + cg]     = rsLo;
        srsum[(m0 + gr + 8) * 2 + cg] = rsHi;
    }
    __syncthreads();

    int rowLo = m0 + gr, rowHi = rowLo + 8;
    float tLo = srsum[rowLo * 2] + srsum[rowLo * 2 + 1];
    float tHi = srsum[rowHi * 2] + srsum[rowHi * 2 + 1];
    float invLo = (tLo > 0.0f) ? 1.0f / tLo : 1.0f;
    float invHi = (tHi > 0.0f) ? 1.0f / tHi : 1.0f;

    #pragma unroll
    for (int nt = 0; nt < 4; nt++) {
        int c = cg * 32 + nt * 8 + tg * 2;
        *(float2*)(out + (size_t)(r0 + rowLo) * 64 + c) =
            make_float2(vlo[nt].x * invLo, vlo[nt].y * invLo);
        *(float2*)(out + (size_t)(r0 + rowHi) * 64 + c) =
            make_float2(vhi[nt].x * invHi, vhi[nt].y * invHi);
    }
}

// ---------------- launch ----------------
extern "C" void kernel_launch(void* const* d_in, const int* in_sizes, int n_in,
                              void* d_out, int out_size) {
    const float* inputs      = (const float*)d_in[0];
    const float* identifiers = (const float*)d_in[1];
    const float* enhancers   = (const float*)d_in[2];
    const float* inhibitors  = (const float*)d_in[3];
    const float* beta        = (const float*)d_in[4];
    const float* delta       = (const float*)d_in[5];
    (void)in_sizes; (void)n_in; (void)out_size;

    cudaFuncSetAttribute(k_gemm, cudaFuncAttributeMaxDynamicSharedMemorySize, SMTOT);

    k_init<<<828, 256>>>(identifiers, enhancers, inhibitors, beta);
    k_warm<<<1, 1024>>>(delta);
    k_gemm<<<256, 256, SMTOT>>>(inputs, delta, (float*)d_out);
}